// round 3
// baseline (speedup 1.0000x reference)
#include <cuda_runtime.h>
#include <math.h>

#define PB 16
#define PP 64
#define PDe 512
#define PF 128
#define PH 8
#define PHS 64
#define PDM 512
#define PBP 1024

typedef unsigned long long u64;

// ---------------- packed f32x2 helpers (FFMA2 — 2x fp32 throughput) ----------------
__device__ __forceinline__ u64 pack_dup(float x) {
    u64 r; asm("mov.b64 %0, {%1, %1};" : "=l"(r) : "f"(x)); return r;
}
__device__ __forceinline__ void ffma2(u64& d, u64 a, u64 b) {
    asm("fma.rn.f32x2 %0, %1, %2, %3;" : "=l"(d) : "l"(a), "l"(b), "l"(d));
}
__device__ __forceinline__ void unpack2(float& lo, float& hi, u64 v) {
    asm("mov.b64 {%0, %1}, %2;" : "=f"(lo), "=f"(hi) : "l"(v));
}

// ---------------- scratch ----------------
__device__ float g_q [PBP * PDM];
__device__ float g_kb[PBP * PDM];
__device__ float g_vb[PBP * PDM];
__device__ float g_qk[PBP * PH * PF];
__device__ float g_sb[PB * PH * PP * PP];
__device__ float g_at[PB * PH * PP * PP];
__device__ float g_ar[PBP * PH * PF];
__device__ float g_cb[PBP * PDM];

// ---------------- 64x64-tile fp32 GEMM, K=512, double-buffered, FFMA2 ----------------
// C[m0:m0+64, n0:n0+64] = A[m0:, 0:512] @ W[0:512, n0:]
__device__ __forceinline__ void gemm64_body(const float* __restrict__ A,
                                            const float* __restrict__ W,
                                            float* __restrict__ C,
                                            int m0, int n0)
{
    __shared__ float As[2][16][64];   // [buf][k][m]  (k-major)
    __shared__ float Bs[2][16][64];   // [buf][k][n]
    const int tid = threadIdx.x;
    const int tx = tid & 15, ty = tid >> 4;
    const int ar = tid >> 2, ac4 = tid & 3;       // A: row, k-chunk(float4)
    const int br = tid >> 4, bc = (tid & 15) * 4; // B: k-row, col

    ulonglong2 acc[4];
#pragma unroll
    for (int i = 0; i < 4; i++) acc[i] = make_ulonglong2(0ull, 0ull);

    // prologue: ktile 0
    {
        float4 va = *(const float4*)(A + (size_t)(m0 + ar) * 512 + ac4 * 4);
        float4 vb = *(const float4*)(W + (size_t)br * 512 + n0 + bc);
        As[0][ac4 * 4 + 0][ar] = va.x; As[0][ac4 * 4 + 1][ar] = va.y;
        As[0][ac4 * 4 + 2][ar] = va.z; As[0][ac4 * 4 + 3][ar] = va.w;
        *(float4*)&Bs[0][br][bc] = vb;
    }
    __syncthreads();

    int buf = 0;
    for (int kt = 0; kt < 32; kt++) {
        float4 na, nb;
        if (kt < 31) {
            int k0 = (kt + 1) * 16;
            na = *(const float4*)(A + (size_t)(m0 + ar) * 512 + k0 + ac4 * 4);
            nb = *(const float4*)(W + (size_t)(k0 + br) * 512 + n0 + bc);
        }
#pragma unroll
        for (int k = 0; k < 16; k++) {
            float4 a4 = *(const float4*)&As[buf][k][ty * 4];
            float4 b4 = *(const float4*)&Bs[buf][k][tx * 4];
            u64 bp0 = *(u64*)&b4.x, bp1 = *(u64*)&b4.z;
            u64 a0 = pack_dup(a4.x), a1 = pack_dup(a4.y);
            u64 a2 = pack_dup(a4.z), a3 = pack_dup(a4.w);
            ffma2(acc[0].x, a0, bp0); ffma2(acc[0].y, a0, bp1);
            ffma2(acc[1].x, a1, bp0); ffma2(acc[1].y, a1, bp1);
            ffma2(acc[2].x, a2, bp0); ffma2(acc[2].y, a2, bp1);
            ffma2(acc[3].x, a3, bp0); ffma2(acc[3].y, a3, bp1);
        }
        if (kt < 31) {
            As[buf ^ 1][ac4 * 4 + 0][ar] = na.x; As[buf ^ 1][ac4 * 4 + 1][ar] = na.y;
            As[buf ^ 1][ac4 * 4 + 2][ar] = na.z; As[buf ^ 1][ac4 * 4 + 3][ar] = na.w;
            *(float4*)&Bs[buf ^ 1][br][bc] = nb;
            __syncthreads();
            buf ^= 1;
        }
    }
#pragma unroll
    for (int i = 0; i < 4; i++)
        *(float4*)(C + (size_t)(m0 + ty * 4 + i) * 512 + n0 + tx * 4) = *(float4*)&acc[i];
}

// K1: projections
__global__ void __launch_bounds__(256) proj_kernel(const float* __restrict__ pe,
                                                   const float* __restrict__ Wq,
                                                   const float* __restrict__ Wk,
                                                   const float* __restrict__ Wv)
{
    const float* W = (blockIdx.z == 0) ? Wq : (blockIdx.z == 1) ? Wk : Wv;
    float* C = (blockIdx.z == 0) ? g_q : (blockIdx.z == 1) ? g_kb : g_vb;
    gemm64_body(pe, W, C, blockIdx.y * 64, blockIdx.x * 64);
}

// K7: final projection
__global__ void __launch_bounds__(256) final_kernel(const float* __restrict__ Wo,
                                                    float* __restrict__ out)
{
    gemm64_body(g_cb, Wo, out, blockIdx.y * 64, blockIdx.x * 64);
}

// K2: qk[m][h][f] = sum_d q[m][h*64+d] * Wk[512+f][h*64+d]
__global__ void __launch_bounds__(256) qk_kernel(const float* __restrict__ Wk)
{
    const int h = blockIdx.y;
    const int m0 = blockIdx.x * 64;
    __shared__ float Qt[64 * 68];   // [d][m]
    __shared__ float Wt[64 * 68];   // [d][f_local]
    const int tid = threadIdx.x, tx = tid & 15, ty = tid >> 4;
    const int lr = tid >> 4, lc4 = tid & 15;

#pragma unroll
    for (int i = 0; i < 4; i++) {
        int r = i * 16 + lr;
        float4 v = *(const float4*)(g_q + (size_t)(m0 + r) * 512 + h * 64 + lc4 * 4);
        Qt[(lc4 * 4 + 0) * 68 + r] = v.x; Qt[(lc4 * 4 + 1) * 68 + r] = v.y;
        Qt[(lc4 * 4 + 2) * 68 + r] = v.z; Qt[(lc4 * 4 + 3) * 68 + r] = v.w;
    }
    for (int fc = 0; fc < 2; fc++) {
        __syncthreads();
#pragma unroll
        for (int i = 0; i < 4; i++) {
            int f = i * 16 + lr;
            float4 v = *(const float4*)(Wk + (size_t)(512 + fc * 64 + f) * 512 + h * 64 + lc4 * 4);
            Wt[(lc4 * 4 + 0) * 68 + f] = v.x; Wt[(lc4 * 4 + 1) * 68 + f] = v.y;
            Wt[(lc4 * 4 + 2) * 68 + f] = v.z; Wt[(lc4 * 4 + 3) * 68 + f] = v.w;
        }
        __syncthreads();
        ulonglong2 acc[4];
#pragma unroll
        for (int i = 0; i < 4; i++) acc[i] = make_ulonglong2(0ull, 0ull);
#pragma unroll
        for (int d = 0; d < 64; d++) {
            float4 a4 = *(const float4*)&Qt[d * 68 + ty * 4];
            float4 b4 = *(const float4*)&Wt[d * 68 + tx * 4];
            u64 bp0 = *(u64*)&b4.x, bp1 = *(u64*)&b4.z;
            u64 a0 = pack_dup(a4.x), a1 = pack_dup(a4.y);
            u64 a2 = pack_dup(a4.z), a3 = pack_dup(a4.w);
            ffma2(acc[0].x, a0, bp0); ffma2(acc[0].y, a0, bp1);
            ffma2(acc[1].x, a1, bp0); ffma2(acc[1].y, a1, bp1);
            ffma2(acc[2].x, a2, bp0); ffma2(acc[2].y, a2, bp1);
            ffma2(acc[3].x, a3, bp0); ffma2(acc[3].y, a3, bp1);
        }
#pragma unroll
        for (int i = 0; i < 4; i++)
            *(float4*)(g_qk + (size_t)(m0 + ty * 4 + i) * (PH * PF) + h * PF + fc * 64 + tx * 4) =
                *(float4*)&acc[i];
    }
}

// K3: scores_base[b][h][q][p] (unscaled)
__global__ void __launch_bounds__(256) sbase_kernel()
{
    const int b = blockIdx.x, h = blockIdx.y;
    __shared__ float Qt[64 * 68];   // [d][q]
    __shared__ float Kt[64 * 68];   // [d][p]
    const int tid = threadIdx.x, tx = tid & 15, ty = tid >> 4;
    const int lr = tid >> 4, lc4 = tid & 15;

#pragma unroll
    for (int i = 0; i < 4; i++) {
        int r = i * 16 + lr;
        float4 vq = *(const float4*)(g_q  + (size_t)(b * 64 + r) * 512 + h * 64 + lc4 * 4);
        float4 vk = *(const float4*)(g_kb + (size_t)(b * 64 + r) * 512 + h * 64 + lc4 * 4);
        Qt[(lc4 * 4 + 0) * 68 + r] = vq.x; Qt[(lc4 * 4 + 1) * 68 + r] = vq.y;
        Qt[(lc4 * 4 + 2) * 68 + r] = vq.z; Qt[(lc4 * 4 + 3) * 68 + r] = vq.w;
        Kt[(lc4 * 4 + 0) * 68 + r] = vk.x; Kt[(lc4 * 4 + 1) * 68 + r] = vk.y;
        Kt[(lc4 * 4 + 2) * 68 + r] = vk.z; Kt[(lc4 * 4 + 3) * 68 + r] = vk.w;
    }
    __syncthreads();

    ulonglong2 acc[4];
#pragma unroll
    for (int i = 0; i < 4; i++) acc[i] = make_ulonglong2(0ull, 0ull);
#pragma unroll
    for (int d = 0; d < 64; d++) {
        float4 a4 = *(const float4*)&Qt[d * 68 + ty * 4];
        float4 b4 = *(const float4*)&Kt[d * 68 + tx * 4];
        u64 bp0 = *(u64*)&b4.x, bp1 = *(u64*)&b4.z;
        u64 a0 = pack_dup(a4.x), a1 = pack_dup(a4.y);
        u64 a2 = pack_dup(a4.z), a3 = pack_dup(a4.w);
        ffma2(acc[0].x, a0, bp0); ffma2(acc[0].y, a0, bp1);
        ffma2(acc[1].x, a1, bp0); ffma2(acc[1].y, a1, bp1);
        ffma2(acc[2].x, a2, bp0); ffma2(acc[2].y, a2, bp1);
        ffma2(acc[3].x, a3, bp0); ffma2(acc[3].y, a3, bp1);
    }
    float* out = g_sb + (size_t)((b * 8 + h) * 64) * 64;
#pragma unroll
    for (int i = 0; i < 4; i++)
        *(float4*)(out + (ty * 4 + i) * 64 + tx * 4) = *(float4*)&acc[i];
}

// K4: fused per-(b,q): scores_rel + softmax + ar, rf read once. 3 blocks/SM target.
__global__ void __launch_bounds__(256, 3) attn_kernel(const float* __restrict__ rf)
{
    const int bq = blockIdx.x;
    const int b = bq >> 6, q = bq & 63;
    __shared__ float rf_s[64 * 132];
    __shared__ float qk_s[8 * 132];
    __shared__ float s_s [8 * 64];
    __shared__ float at_s[8 * 68];
    const int tid = threadIdx.x;

    const float4* rfg = (const float4*)(rf + (size_t)bq * 8192);
    float4* rf4 = (float4*)rf_s;
#pragma unroll
    for (int i = 0; i < 8; i++) {
        int idx = i * 256 + tid;
        rf4[(idx >> 5) * 33 + (idx & 31)] = rfg[idx];
    }
    ((float4*)qk_s)[(tid >> 5) * 33 + (tid & 31)] =
        ((const float4*)(g_qk + (size_t)bq * (PH * PF)))[tid];
    __syncthreads();

    // scores: s[h][p] = 0.125*(sbase + qk[h]·rf[p])
#pragma unroll
    for (int rep = 0; rep < 2; rep++) {
        int o = rep * 256 + tid;
        int h = o >> 6, p = o & 63;
        const float4* qr = (const float4*)qk_s + h * 33;
        const float4* rr = rf4 + p * 33;
        u64 acc2 = 0ull;
#pragma unroll 8
        for (int f4 = 0; f4 < 32; f4++) {
            float4 a = qr[f4], r = rr[f4];
            ffma2(acc2, *(u64*)&a.x, *(u64*)&r.x);
            ffma2(acc2, *(u64*)&a.z, *(u64*)&r.z);
        }
        float lo, hi; unpack2(lo, hi, acc2);
        float sb = g_sb[(size_t)((b * 8 + h) * 64 + q) * 64 + p];
        s_s[h * 64 + p] = 0.125f * (lo + hi + sb);
    }
    __syncthreads();

    // softmax: warp w -> head w
    {
        int w = tid >> 5, l = tid & 31;
        float v0 = s_s[w * 64 + l], v1 = s_s[w * 64 + 32 + l];
        float m = fmaxf(v0, v1);
#pragma unroll
        for (int off = 16; off; off >>= 1) m = fmaxf(m, __shfl_xor_sync(0xffffffffu, m, off));
        float e0 = __expf(v0 - m), e1 = __expf(v1 - m);
        float s = e0 + e1;
#pragma unroll
        for (int off = 16; off; off >>= 1) s += __shfl_xor_sync(0xffffffffu, s, off);
        float inv = 1.f / s;
        float a0 = e0 * inv, a1 = e1 * inv;
        at_s[w * 68 + l] = a0; at_s[w * 68 + 32 + l] = a1;
        float* ag = g_at + (size_t)((b * 8 + w) * 64 + q) * 64;
        ag[l] = a0; ag[32 + l] = a1;
    }
    __syncthreads();

    // ar[h][f] = attn[h]·rf[:,f]
    {
        int h = tid >> 5, f4 = tid & 31;
        const float* ah = at_s + h * 68;
        ulonglong2 acc = make_ulonglong2(0ull, 0ull);
#pragma unroll 8
        for (int p = 0; p < 64; p++) {
            u64 ad = pack_dup(ah[p]);
            float4 r = rf4[p * 33 + f4];
            ffma2(acc.x, ad, *(u64*)&r.x);
            ffma2(acc.y, ad, *(u64*)&r.z);
        }
        ((float4*)(g_ar + (size_t)bq * (PH * PF)))[tid] = *(float4*)&acc;
    }
}

// K5: out_rel -> g_cb
__global__ void __launch_bounds__(256) outrel_kernel(const float* __restrict__ Wv)
{
    const int h = blockIdx.y;
    const int m0 = blockIdx.x * 64;
    __shared__ float At[64 * 68];  // [f_local][m]
    __shared__ float Bs[64 * 68];  // [f_local][d]
    const int tid = threadIdx.x, tx = tid & 15, ty = tid >> 4;
    const int lr = tid >> 4, lc4 = tid & 15;
    ulonglong2 acc[4];
#pragma unroll
    for (int i = 0; i < 4; i++) acc[i] = make_ulonglong2(0ull, 0ull);

    for (int fc = 0; fc < 2; fc++) {
        __syncthreads();
#pragma unroll
        for (int i = 0; i < 4; i++) {
            int r = i * 16 + lr;
            float4 va = *(const float4*)(g_ar + (size_t)(m0 + r) * (PH * PF) + h * PF + fc * 64 + lc4 * 4);
            At[(lc4 * 4 + 0) * 68 + r] = va.x; At[(lc4 * 4 + 1) * 68 + r] = va.y;
            At[(lc4 * 4 + 2) * 68 + r] = va.z; At[(lc4 * 4 + 3) * 68 + r] = va.w;
            *(float4*)&Bs[r * 68 + lc4 * 4] =
                *(const float4*)(Wv + (size_t)(512 + fc * 64 + r) * 512 + h * 64 + lc4 * 4);
        }
        __syncthreads();
#pragma unroll
        for (int f = 0; f < 64; f++) {
            float4 a4 = *(const float4*)&At[f * 68 + ty * 4];
            float4 b4 = *(const float4*)&Bs[f * 68 + tx * 4];
            u64 bp0 = *(u64*)&b4.x, bp1 = *(u64*)&b4.z;
            u64 a0 = pack_dup(a4.x), a1 = pack_dup(a4.y);
            u64 a2 = pack_dup(a4.z), a3 = pack_dup(a4.w);
            ffma2(acc[0].x, a0, bp0); ffma2(acc[0].y, a0, bp1);
            ffma2(acc[1].x, a1, bp0); ffma2(acc[1].y, a1, bp1);
            ffma2(acc[2].x, a2, bp0); ffma2(acc[2].y, a2, bp1);
            ffma2(acc[3].x, a3, bp0); ffma2(acc[3].y, a3, bp1);
        }
    }
#pragma unroll
    for (int i = 0; i < 4; i++)
        *(float4*)(g_cb + (size_t)(m0 + ty * 4 + i) * 512 + h * 64 + tx * 4) = *(float4*)&acc[i];
}

// K6: out_base accumulate into g_cb
__global__ void __launch_bounds__(256) outbase_kernel()
{
    const int b = blockIdx.x, h = blockIdx.y;
    __shared__ float At[64 * 68];  // [p][q]
    __shared__ float Vs[64 * 68];  // [p][d]
    const int tid = threadIdx.x, tx = tid & 15, ty = tid >> 4;
    const int lr = tid >> 4, lc4 = tid & 15;

#pragma unroll
    for (int i = 0; i < 4; i++) {
        int r = i * 16 + lr;
        float4 va = *(const float4*)(g_at + (size_t)((b * 8 + h) * 64 + r) * 64 + lc4 * 4);
        At[(lc4 * 4 + 0) * 68 + r] = va.x; At[(lc4 * 4 + 1) * 68 + r] = va.y;
        At[(lc4 * 4 + 2) * 68 + r] = va.z; At[(lc4 * 4 + 3) * 68 + r] = va.w;
        *(float4*)&Vs[r * 68 + lc4 * 4] =
            *(const float4*)(g_vb + (size_t)(b * 64 + r) * 512 + h * 64 + lc4 * 4);
    }
    __syncthreads();

    ulonglong2 acc[4];
#pragma unroll
    for (int i = 0; i < 4; i++) acc[i] = make_ulonglong2(0ull, 0ull);
#pragma unroll
    for (int p = 0; p < 64; p++) {
        float4 a4 = *(const float4*)&At[p * 68 + ty * 4];
        float4 b4 = *(const float4*)&Vs[p * 68 + tx * 4];
        u64 bp0 = *(u64*)&b4.x, bp1 = *(u64*)&b4.z;
        u64 a0 = pack_dup(a4.x), a1 = pack_dup(a4.y);
        u64 a2 = pack_dup(a4.z), a3 = pack_dup(a4.w);
        ffma2(acc[0].x, a0, bp0); ffma2(acc[0].y, a0, bp1);
        ffma2(acc[1].x, a1, bp0); ffma2(acc[1].y, a1, bp1);
        ffma2(acc[2].x, a2, bp0); ffma2(acc[2].y, a2, bp1);
        ffma2(acc[3].x, a3, bp0); ffma2(acc[3].y, a3, bp1);
    }
#pragma unroll
    for (int i = 0; i < 4; i++) {
        float* cp = g_cb + (size_t)(b * 64 + ty * 4 + i) * 512 + h * 64 + tx * 4;
        float4 old = *(float4*)cp;
        float4 av = *(float4*)&acc[i];
        old.x += av.x; old.y += av.y; old.z += av.z; old.w += av.w;
        *(float4*)cp = old;
    }
}

extern "C" void kernel_launch(void* const* d_in, const int* in_sizes, int n_in,
                              void* d_out, int out_size)
{
    (void)in_sizes; (void)n_in; (void)out_size;
    const float* pe = (const float*)d_in[0];
    const float* rf = (const float*)d_in[1];
    const float* Wq = (const float*)d_in[3];
    const float* Wk = (const float*)d_in[4];
    const float* Wv = (const float*)d_in[5];
    const float* Wo = (const float*)d_in[6];
    float* out = (float*)d_out;

    dim3 t(256);
    proj_kernel   <<<dim3(8, 16, 3), t>>>(pe, Wq, Wk, Wv);
    qk_kernel     <<<dim3(16, 8),    t>>>(Wk);
    sbase_kernel  <<<dim3(16, 8),    t>>>();
    attn_kernel   <<<dim3(1024),     t>>>(rf);
    outrel_kernel <<<dim3(16, 8),    t>>>(Wv);
    outbase_kernel<<<dim3(16, 8),    t>>>();
    final_kernel  <<<dim3(8, 16),    t>>>(Wo, out);
}

// round 5
// speedup vs baseline: 1.2275x; 1.2275x over previous
#include <cuda_runtime.h>
#include <cuda_bf16.h>
#include <cstdint>
#include <math.h>

#define PB 16
#define PP 64
#define PF 128
#define PH 8
#define PDM 512
#define PBP 1024

typedef unsigned long long u64;

// ================= packed f32x2 helpers =================
__device__ __forceinline__ u64 pack_dup(float x) {
    u64 r; asm("mov.b64 %0, {%1, %1};" : "=l"(r) : "f"(x)); return r;
}
__device__ __forceinline__ void ffma2(u64& d, u64 a, u64 b) {
    asm("fma.rn.f32x2 %0, %1, %2, %3;" : "=l"(d) : "l"(a), "l"(b), "l"(d));
}
__device__ __forceinline__ void unpack2(float& lo, float& hi, u64 v) {
    asm("mov.b64 {%0, %1}, %2;" : "=f"(lo), "=f"(hi) : "l"(v));
}

__device__ __forceinline__ uint32_t smem_to_u32(const void* p) {
    uint32_t a;
    asm("{ .reg .u64 t; cvta.to.shared.u64 t, %1; cvt.u32.u64 %0, t; }" : "=r"(a) : "l"(p));
    return a;
}

#define SW128(o) ((o) ^ (((o) >> 3) & 0x70))

// ldmatrix x4 (baseline PTX, sm_75+)
#define LDMX4(r, a) \
    asm volatile("ldmatrix.sync.aligned.m8n8.x4.shared.b16 {%0,%1,%2,%3}, [%4];" \
        : "=r"((r)[0]), "=r"((r)[1]), "=r"((r)[2]), "=r"((r)[3]) : "r"(a))

// mma.sync bf16 (baseline PTX, sm_80+)
#define MMA_BF16(c, a, b) \
    asm volatile("mma.sync.aligned.m16n8k16.row.col.f32.bf16.bf16.f32 " \
        "{%0,%1,%2,%3}, {%4,%5,%6,%7}, {%8,%9}, {%0,%1,%2,%3};" \
        : "+f"((c)[0]), "+f"((c)[1]), "+f"((c)[2]), "+f"((c)[3]) \
        : "r"((a)[0]), "r"((a)[1]), "r"((a)[2]), "r"((a)[3]), "r"((b)[0]), "r"((b)[1]))

// ================= scratch =================
__device__ float g_q [PBP * PDM];
__device__ float g_kb[PBP * PDM];
__device__ float g_vb[PBP * PDM];
__device__ float g_qk[PBP * PH * PF];
__device__ float g_sb[PB * PH * PP * PP];
__device__ float g_at[PB * PH * PP * PP];
__device__ float g_ar[PBP * PH * PF];
__device__ __nv_bfloat16 g_pe_hi[PBP * PDM];
__device__ __nv_bfloat16 g_pe_lo[PBP * PDM];
__device__ __nv_bfloat16 g_cb_hi[PBP * PDM];
__device__ __nv_bfloat16 g_cb_lo[PBP * PDM];
__device__ __nv_bfloat16 g_wt_hi[4 * 512 * 512];  // transposed [n][k]: Wq,Wk0,Wv0,Wo
__device__ __nv_bfloat16 g_wt_lo[4 * 512 * 512];

__device__ __forceinline__ void bsplit(float x, __nv_bfloat16& h, __nv_bfloat16& l)
{
    h = __float2bfloat16_rn(x);
    l = __float2bfloat16_rn(x - __bfloat162float(h));
}

// ================= conversion kernels =================
__global__ void __launch_bounds__(256) conv_pe_kernel(const float* __restrict__ pe)
{
    int idx = blockIdx.x * 256 + threadIdx.x;  // x4 floats
    float4 v = *(const float4*)(pe + (size_t)idx * 4);
    __nv_bfloat16 h[4], l[4];
    bsplit(v.x, h[0], l[0]); bsplit(v.y, h[1], l[1]);
    bsplit(v.z, h[2], l[2]); bsplit(v.w, h[3], l[3]);
    *(uint2*)(g_pe_hi + (size_t)idx * 4) = *(uint2*)h;
    *(uint2*)(g_pe_lo + (size_t)idx * 4) = *(uint2*)l;
}

// transpose first 512 rows of W[:,512] -> Wt[n][k], bf16 hi/lo
__global__ void __launch_bounds__(256) conv_w_kernel(const float* __restrict__ Wq,
                                                     const float* __restrict__ Wk,
                                                     const float* __restrict__ Wv,
                                                     const float* __restrict__ Wo)
{
    const int z = blockIdx.z;
    const float* W = (z == 0) ? Wq : (z == 1) ? Wk : (z == 2) ? Wv : Wo;
    __shared__ float tile[32][33];
    const int n0 = blockIdx.x * 32, k0 = blockIdx.y * 32;
    const int tx = threadIdx.x & 31, ty = threadIdx.x >> 5;
#pragma unroll
    for (int j = 0; j < 4; j++)
        tile[ty + j * 8][tx] = W[(size_t)(k0 + ty + j * 8) * 512 + n0 + tx];
    __syncthreads();
#pragma unroll
    for (int j = 0; j < 4; j++) {
        float v = tile[tx][ty + j * 8];
        __nv_bfloat16 h, l; bsplit(v, h, l);
        size_t o = (size_t)z * 262144 + (size_t)(n0 + ty + j * 8) * 512 + k0 + tx;
        g_wt_hi[o] = h; g_wt_lo[o] = l;
    }
}

// ================= warp-MMA GEMM: C[m0:+64, n0:+64] = A @ B^T (bf16 hi/lo split) =================
// A: [.][512] bf16 row-major (hi/lo), B: [n][k] bf16 (hi/lo), C: [.][512] f32.
// Block = 128 threads (4 warps), warp tile 32x32, K-chunks of 64.
__device__ __forceinline__ void mma_gemm64(const __nv_bfloat16* __restrict__ Ahi,
                                           const __nv_bfloat16* __restrict__ Alo,
                                           const __nv_bfloat16* __restrict__ Bhi,
                                           const __nv_bfloat16* __restrict__ Blo,
                                           float* __restrict__ C, int m0, int n0)
{
    __shared__ __nv_bfloat16 sAh[4096], sAl[4096], sBh[4096], sBl[4096];  // 64 rows x 64 bf16, SW128
    const int tid = threadIdx.x, lane = tid & 31, wid = tid >> 5;
    const int wm = (wid & 1) * 32, wn = (wid >> 1) * 32;
    const int lr = tid >> 1, lh = tid & 1;  // gmem->smem: row, 32-bf16 half

    const uint32_t bAh = smem_to_u32(sAh), bAl = smem_to_u32(sAl);
    const uint32_t bBh = smem_to_u32(sBh), bBl = smem_to_u32(sBl);

    // per-lane ldmatrix coordinates
    const uint32_t rowA = wm + (lane & 15);
    const uint32_t kbA  = (lane >> 4) * 16;
    const uint32_t rowB = wn + (lane & 7) + ((lane >> 4) << 3);
    const uint32_t kbB  = ((lane >> 3) & 1) * 16;

    float c[2][4][4] = {};

    for (int ch = 0; ch < 8; ch++) {
        const int k0 = ch * 64;
        {
            const uint4* gah = (const uint4*)(Ahi + (size_t)(m0 + lr) * 512 + k0 + lh * 32);
            const uint4* gal = (const uint4*)(Alo + (size_t)(m0 + lr) * 512 + k0 + lh * 32);
            const uint4* gbh = (const uint4*)(Bhi + (size_t)(n0 + lr) * 512 + k0 + lh * 32);
            const uint4* gbl = (const uint4*)(Blo + (size_t)(n0 + lr) * 512 + k0 + lh * 32);
#pragma unroll
            for (int j = 0; j < 4; j++) {
                uint32_t o = SW128((uint32_t)(lr * 128 + lh * 64 + j * 16));
                *(uint4*)((char*)sAh + o) = gah[j];
                *(uint4*)((char*)sAl + o) = gal[j];
                *(uint4*)((char*)sBh + o) = gbh[j];
                *(uint4*)((char*)sBl + o) = gbl[j];
            }
        }
        __syncthreads();

#pragma unroll
        for (int ks = 0; ks < 4; ks++) {
            const uint32_t kA = ks * 32 + kbA;
            const uint32_t kB = ks * 32 + kbB;
            const uint32_t oA0 = SW128(rowA * 128 + kA);
            const uint32_t oA1 = SW128((rowA + 16) * 128 + kA);
            const uint32_t oB0 = SW128(rowB * 128 + kB);
            const uint32_t oB1 = SW128((rowB + 16) * 128 + kB);

            uint32_t ah0[4], ah1[4], al0[4], al1[4];
            LDMX4(ah0, bAh + oA0); LDMX4(ah1, bAh + oA1);
            LDMX4(al0, bAl + oA0); LDMX4(al1, bAl + oA1);
            uint32_t bh0[4], bh1[4], bl0[4], bl1[4];
            LDMX4(bh0, bBh + oB0); LDMX4(bh1, bBh + oB1);
            LDMX4(bl0, bBl + oB0); LDMX4(bl1, bBl + oB1);

            uint32_t* Ah[2] = { ah0, ah1 };
            uint32_t* Al[2] = { al0, al1 };
            uint32_t* Bh[4] = { bh0, bh0 + 2, bh1, bh1 + 2 };
            uint32_t* Bl[4] = { bl0, bl0 + 2, bl1, bl1 + 2 };
#pragma unroll
            for (int mt = 0; mt < 2; mt++) {
#pragma unroll
                for (int j = 0; j < 4; j++) {
                    MMA_BF16(c[mt][j], Ah[mt], Bh[j]);
                    MMA_BF16(c[mt][j], Ah[mt], Bl[j]);
                    MMA_BF16(c[mt][j], Al[mt], Bh[j]);
                }
            }
        }
        __syncthreads();
    }

    // epilogue: fragment (g = lane>>2, cc = (lane&3)*2)
    const int g = lane >> 2, cc = (lane & 3) * 2;
#pragma unroll
    for (int mt = 0; mt < 2; mt++)
#pragma unroll
        for (int j = 0; j < 4; j++) {
            int row = m0 + wm + mt * 16 + g;
            int col = n0 + wn + j * 8 + cc;
            *(float2*)(C + (size_t)row * 512 + col) = make_float2(c[mt][j][0], c[mt][j][1]);
            *(float2*)(C + (size_t)(row + 8) * 512 + col) = make_float2(c[mt][j][2], c[mt][j][3]);
        }
}

__global__ void __launch_bounds__(128) proj_mma_kernel()
{
    const int z = blockIdx.z;
    float* C = (z == 0) ? g_q : (z == 1) ? g_kb : g_vb;
    mma_gemm64(g_pe_hi, g_pe_lo, g_wt_hi + (size_t)z * 262144, g_wt_lo + (size_t)z * 262144,
               C, blockIdx.y * 64, blockIdx.x * 64);
}

__global__ void __launch_bounds__(128) final_mma_kernel(float* __restrict__ out)
{
    mma_gemm64(g_cb_hi, g_cb_lo, g_wt_hi + 3 * 262144, g_wt_lo + 3 * 262144,
               out, blockIdx.y * 64, blockIdx.x * 64);
}

// ================= K2: qk[m][h][f] = sum_d q[m][h*64+d] * Wk[512+f][h*64+d] =================
__global__ void __launch_bounds__(256) qk_kernel(const float* __restrict__ Wk)
{
    const int h = blockIdx.y;
    const int m0 = blockIdx.x * 64;
    __shared__ float Qt[64 * 68];
    __shared__ float Wt[64 * 68];
    const int tid = threadIdx.x, tx = tid & 15, ty = tid >> 4;
    const int lr = tid >> 4, lc4 = tid & 15;

#pragma unroll
    for (int i = 0; i < 4; i++) {
        int r = i * 16 + lr;
        float4 v = *(const float4*)(g_q + (size_t)(m0 + r) * 512 + h * 64 + lc4 * 4);
        Qt[(lc4 * 4 + 0) * 68 + r] = v.x; Qt[(lc4 * 4 + 1) * 68 + r] = v.y;
        Qt[(lc4 * 4 + 2) * 68 + r] = v.z; Qt[(lc4 * 4 + 3) * 68 + r] = v.w;
    }
    for (int fc = 0; fc < 2; fc++) {
        __syncthreads();
#pragma unroll
        for (int i = 0; i < 4; i++) {
            int f = i * 16 + lr;
            float4 v = *(const float4*)(Wk + (size_t)(512 + fc * 64 + f) * 512 + h * 64 + lc4 * 4);
            Wt[(lc4 * 4 + 0) * 68 + f] = v.x; Wt[(lc4 * 4 + 1) * 68 + f] = v.y;
            Wt[(lc4 * 4 + 2) * 68 + f] = v.z; Wt[(lc4 * 4 + 3) * 68 + f] = v.w;
        }
        __syncthreads();
        ulonglong2 acc[4];
#pragma unroll
        for (int i = 0; i < 4; i++) acc[i] = make_ulonglong2(0ull, 0ull);
#pragma unroll
        for (int d = 0; d < 64; d++) {
            float4 a4 = *(const float4*)&Qt[d * 68 + ty * 4];
            float4 b4 = *(const float4*)&Wt[d * 68 + tx * 4];
            u64 bp0 = *(u64*)&b4.x, bp1 = *(u64*)&b4.z;
            u64 a0 = pack_dup(a4.x), a1 = pack_dup(a4.y);
            u64 a2 = pack_dup(a4.z), a3 = pack_dup(a4.w);
            ffma2(acc[0].x, a0, bp0); ffma2(acc[0].y, a0, bp1);
            ffma2(acc[1].x, a1, bp0); ffma2(acc[1].y, a1, bp1);
            ffma2(acc[2].x, a2, bp0); ffma2(acc[2].y, a2, bp1);
            ffma2(acc[3].x, a3, bp0); ffma2(acc[3].y, a3, bp1);
        }
#pragma unroll
        for (int i = 0; i < 4; i++)
            *(float4*)(g_qk + (size_t)(m0 + ty * 4 + i) * (PH * PF) + h * PF + fc * 64 + tx * 4) =
                *(float4*)&acc[i];
    }
}

// ================= K3: scores_base =================
__global__ void __launch_bounds__(256) sbase_kernel()
{
    const int b = blockIdx.x, h = blockIdx.y;
    __shared__ float Qt[64 * 68];
    __shared__ float Kt[64 * 68];
    const int tid = threadIdx.x, tx = tid & 15, ty = tid >> 4;
    const int lr = tid >> 4, lc4 = tid & 15;

#pragma unroll
    for (int i = 0; i < 4; i++) {
        int r = i * 16 + lr;
        float4 vq = *(const float4*)(g_q  + (size_t)(b * 64 + r) * 512 + h * 64 + lc4 * 4);
        float4 vk = *(const float4*)(g_kb + (size_t)(b * 64 + r) * 512 + h * 64 + lc4 * 4);
        Qt[(lc4 * 4 + 0) * 68 + r] = vq.x; Qt[(lc4 * 4 + 1) * 68 + r] = vq.y;
        Qt[(lc4 * 4 + 2) * 68 + r] = vq.z; Qt[(lc4 * 4 + 3) * 68 + r] = vq.w;
        Kt[(lc4 * 4 + 0) * 68 + r] = vk.x; Kt[(lc4 * 4 + 1) * 68 + r] = vk.y;
        Kt[(lc4 * 4 + 2) * 68 + r] = vk.z; Kt[(lc4 * 4 + 3) * 68 + r] = vk.w;
    }
    __syncthreads();

    ulonglong2 acc[4];
#pragma unroll
    for (int i = 0; i < 4; i++) acc[i] = make_ulonglong2(0ull, 0ull);
#pragma unroll
    for (int d = 0; d < 64; d++) {
        float4 a4 = *(const float4*)&Qt[d * 68 + ty * 4];
        float4 b4 = *(const float4*)&Kt[d * 68 + tx * 4];
        u64 bp0 = *(u64*)&b4.x, bp1 = *(u64*)&b4.z;
        u64 a0 = pack_dup(a4.x), a1 = pack_dup(a4.y);
        u64 a2 = pack_dup(a4.z), a3 = pack_dup(a4.w);
        ffma2(acc[0].x, a0, bp0); ffma2(acc[0].y, a0, bp1);
        ffma2(acc[1].x, a1, bp0); ffma2(acc[1].y, a1, bp1);
        ffma2(acc[2].x, a2, bp0); ffma2(acc[2].y, a2, bp1);
        ffma2(acc[3].x, a3, bp0); ffma2(acc[3].y, a3, bp1);
    }
    float* out = g_sb + (size_t)((b * 8 + h) * 64) * 64;
#pragma unroll
    for (int i = 0; i < 4; i++)
        *(float4*)(out + (ty * 4 + i) * 64 + tx * 4) = *(float4*)&acc[i];
}

// ================= K4: fused attn (scores_rel + softmax + ar) =================
__global__ void __launch_bounds__(256, 3) attn_kernel(const float* __restrict__ rf)
{
    const int bq = blockIdx.x;
    const int b = bq >> 6, q = bq & 63;
    __shared__ float rf_s[64 * 132];
    __shared__ float qk_s[8 * 132];
    __shared__ float s_s [8 * 64];
    __shared__ float at_s[8 * 68];
    const int tid = threadIdx.x;

    const float4* rfg = (const float4*)(rf + (size_t)bq * 8192);
    float4* rf4 = (float4*)rf_s;
#pragma unroll
    for (int i = 0; i < 8; i++) {
        int idx = i * 256 + tid;
        rf4[(idx >> 5) * 33 + (idx & 31)] = rfg[idx];
    }
    ((float4*)qk_s)[(tid >> 5) * 33 + (tid & 31)] =
        ((const float4*)(g_qk + (size_t)bq * (PH * PF)))[tid];
    __syncthreads();

    // scores: warp covers 8 h x 4 p -> rf reads become 4-address + broadcast
#pragma unroll
    for (int rep = 0; rep < 2; rep++) {
        int o = rep * 256 + tid;
        int h = o & 7, p = o >> 3;
        const float4* qr = (const float4*)qk_s + h * 33;
        const float4* rr = rf4 + p * 33;
        u64 acc2 = 0ull;
#pragma unroll 8
        for (int f4 = 0; f4 < 32; f4++) {
            float4 a = qr[f4], r = rr[f4];
            ffma2(acc2, *(u64*)&a.x, *(u64*)&r.x);
            ffma2(acc2, *(u64*)&a.z, *(u64*)&r.z);
        }
        float lo, hi; unpack2(lo, hi, acc2);
        float sbv = g_sb[(size_t)((b * 8 + h) * 64 + q) * 64 + p];
        s_s[h * 64 + p] = 0.125f * (lo + hi + sbv);
    }
    __syncthreads();

    {
        int w = tid >> 5, l = tid & 31;
        float v0 = s_s[w * 64 + l], v1 = s_s[w * 64 + 32 + l];
        float m = fmaxf(v0, v1);
#pragma unroll
        for (int off = 16; off; off >>= 1) m = fmaxf(m, __shfl_xor_sync(0xffffffffu, m, off));
        float e0 = __expf(v0 - m), e1 = __expf(v1 - m);
        float s = e0 + e1;
#pragma unroll
        for (int off = 16; off; off >>= 1) s += __shfl_xor_sync(0xffffffffu, s, off);
        float inv = 1.f / s;
        float a0 = e0 * inv, a1 = e1 * inv;
        at_s[w * 68 + l] = a0; at_s[w * 68 + 32 + l] = a1;
        float* ag = g_at + (size_t)((b * 8 + w) * 64 + q) * 64;
        ag[l] = a0; ag[32 + l] = a1;
    }
    __syncthreads();

    {
        int h = tid >> 5, f4 = tid & 31;
        const float* ah = at_s + h * 68;
        ulonglong2 acc = make_ulonglong2(0ull, 0ull);
#pragma unroll 8
        for (int p = 0; p < 64; p++) {
            u64 ad = pack_dup(ah[p]);
            float4 r = rf4[p * 33 + f4];
            ffma2(acc.x, ad, *(u64*)&r.x);
            ffma2(acc.y, ad, *(u64*)&r.z);
        }
        ((float4*)(g_ar + (size_t)bq * (PH * PF)))[tid] = *(float4*)&acc;
    }
}

// ================= K5+K6 merged: cb = attn@v_base + ar@Wv_f -> bf16 hi/lo =================
__global__ void __launch_bounds__(256) outmerge_kernel(const float* __restrict__ Wv)
{
    const int b = blockIdx.x, h = blockIdx.y;
    __shared__ float S1[64 * 68];
    __shared__ float S2[64 * 68];
    const int tid = threadIdx.x, tx = tid & 15, ty = tid >> 4;
    const int lr = tid >> 4, lc4 = tid & 15;

    ulonglong2 acc[4];
#pragma unroll
    for (int i = 0; i < 4; i++) acc[i] = make_ulonglong2(0ull, 0ull);

    // phase A: outbase — S1 = attn^T [p][q], S2 = v_base [p][d]
#pragma unroll
    for (int i = 0; i < 4; i++) {
        int r = i * 16 + lr;
        float4 va = *(const float4*)(g_at + (size_t)((b * 8 + h) * 64 + r) * 64 + lc4 * 4);
        S1[(lc4 * 4 + 0) * 68 + r] = va.x; S1[(lc4 * 4 + 1) * 68 + r] = va.y;
        S1[(lc4 * 4 + 2) * 68 + r] = va.z; S1[(lc4 * 4 + 3) * 68 + r] = va.w;
        *(float4*)&S2[r * 68 + lc4 * 4] =
            *(const float4*)(g_vb + (size_t)(b * 64 + r) * 512 + h * 64 + lc4 * 4);
    }
    __syncthreads();
#pragma unroll
    for (int p = 0; p < 64; p++) {
        float4 a4 = *(const float4*)&S1[p * 68 + ty * 4];
        float4 b4 = *(const float4*)&S2[p * 68 + tx * 4];
        u64 bp0 = *(u64*)&b4.x, bp1 = *(u64*)&b4.z;
        u64 a0 = pack_dup(a4.x), a1 = pack_dup(a4.y);
        u64 a2 = pack_dup(a4.z), a3 = pack_dup(a4.w);
        ffma2(acc[0].x, a0, bp0); ffma2(acc[0].y, a0, bp1);
        ffma2(acc[1].x, a1, bp0); ffma2(acc[1].y, a1, bp1);
        ffma2(acc[2].x, a2, bp0); ffma2(acc[2].y, a2, bp1);
        ffma2(acc[3].x, a3, bp0); ffma2(acc[3].y, a3, bp1);
    }

    // phase B: outrel — S1 = ar^T [f][m], S2 = Wv_f [f][d]
    const int m0 = b * 64;
    for (int fc = 0; fc < 2; fc++) {
        __syncthreads();
#pragma unroll
        for (int i = 0; i < 4; i++) {
            int r = i * 16 + lr;
            float4 va = *(const float4*)(g_ar + (size_t)(m0 + r) * (PH * PF) + h * PF + fc * 64 + lc4 * 4);
            S1[(lc4 * 4 + 0) * 68 + r] = va.x; S1[(lc4 * 4 + 1) * 68 + r] = va.y;
            S1[(lc4 * 4 + 2) * 68 + r] = va.z; S1[(lc4 * 4 + 3) * 68 + r] = va.w;
            *(float4*)&S2[r * 68 + lc4 * 4] =
                *(const float4*)(Wv + (size_t)(512 + fc * 64 + r) * 512 + h * 64 + lc4 * 4);
        }
        __syncthreads();
#pragma unroll
        for (int f = 0; f < 64; f++) {
            float4 a4 = *(const float4*)&S1[f * 68 + ty * 4];
            float4 b4 = *(const float4*)&S2[f * 68 + tx * 4];
            u64 bp0 = *(u64*)&b4.x, bp1 = *(u64*)&b4.z;
            u64 a0 = pack_dup(a4.x), a1 = pack_dup(a4.y);
            u64 a2 = pack_dup(a4.z), a3 = pack_dup(a4.w);
            ffma2(acc[0].x, a0, bp0); ffma2(acc[0].y, a0, bp1);
            ffma2(acc[1].x, a1, bp0); ffma2(acc[1].y, a1, bp1);
            ffma2(acc[2].x, a2, bp0); ffma2(acc[2].y, a2, bp1);
            ffma2(acc[3].x, a3, bp0); ffma2(acc[3].y, a3, bp1);
        }
    }

    // epilogue: bf16 split -> g_cb_hi / g_cb_lo
#pragma unroll
    for (int i = 0; i < 4; i++) {
        float4 v = *(float4*)&acc[i];
        __nv_bfloat16 hb[4], lb[4];
        bsplit(v.x, hb[0], lb[0]); bsplit(v.y, hb[1], lb[1]);
        bsplit(v.z, hb[2], lb[2]); bsplit(v.w, hb[3], lb[3]);
        size_t o = (size_t)(b * 64 + ty * 4 + i) * 512 + h * 64 + tx * 4;
        *(uint2*)(g_cb_hi + o) = *(uint2*)hb;
        *(uint2*)(g_cb_lo + o) = *(uint2*)lb;
    }
}

// ================= launch =================
extern "C" void kernel_launch(void* const* d_in, const int* in_sizes, int n_in,
                              void* d_out, int out_size)
{
    (void)in_sizes; (void)n_in; (void)out_size;
    const float* pe = (const float*)d_in[0];
    const float* rf = (const float*)d_in[1];
    const float* Wq = (const float*)d_in[3];
    const float* Wk = (const float*)d_in[4];
    const float* Wv = (const float*)d_in[5];
    const float* Wo = (const float*)d_in[6];
    float* out = (float*)d_out;

    conv_pe_kernel  <<<512, 256>>>(pe);
    conv_w_kernel   <<<dim3(16, 16, 4), 256>>>(Wq, Wk, Wv, Wo);
    proj_mma_kernel <<<dim3(8, 16, 3), 128>>>();
    qk_kernel       <<<dim3(16, 8), 256>>>(Wk);
    sbase_kernel    <<<dim3(16, 8), 256>>>();
    attn_kernel     <<<dim3(1024), 256>>>(rf);
    outmerge_kernel <<<dim3(16, 8), 256>>>(Wv);
    final_mma_kernel<<<dim3(8, 16), 128>>>(out);
}

// round 6
// speedup vs baseline: 1.2575x; 1.0245x over previous
#include <cuda_runtime.h>
#include <cuda_bf16.h>
#include <cstdint>
#include <math.h>

#define PB 16
#define PP 64
#define PF 128
#define PH 8
#define PDM 512
#define PBP 1024

typedef unsigned long long u64;

// ================= packed f32x2 helpers =================
__device__ __forceinline__ u64 pack_dup(float x) {
    u64 r; asm("mov.b64 %0, {%1, %1};" : "=l"(r) : "f"(x)); return r;
}
__device__ __forceinline__ void ffma2(u64& d, u64 a, u64 b) {
    asm("fma.rn.f32x2 %0, %1, %2, %3;" : "=l"(d) : "l"(a), "l"(b), "l"(d));
}
__device__ __forceinline__ void unpack2(float& lo, float& hi, u64 v) {
    asm("mov.b64 {%0, %1}, %2;" : "=f"(lo), "=f"(hi) : "l"(v));
}

__device__ __forceinline__ uint32_t smem_to_u32(const void* p) {
    uint32_t a;
    asm("{ .reg .u64 t; cvta.to.shared.u64 t, %1; cvt.u32.u64 %0, t; }" : "=r"(a) : "l"(p));
    return a;
}

#define SW128(o) ((o) ^ (((o) >> 3) & 0x70))

// ldmatrix x4 (baseline PTX, sm_75+)
#define LDMX4(r, a) \
    asm volatile("ldmatrix.sync.aligned.m8n8.x4.shared.b16 {%0,%1,%2,%3}, [%4];" \
        : "=r"((r)[0]), "=r"((r)[1]), "=r"((r)[2]), "=r"((r)[3]) : "r"(a))

// mma.sync bf16 (baseline PTX, sm_80+)
#define MMA_BF16(c, a, b) \
    asm volatile("mma.sync.aligned.m16n8k16.row.col.f32.bf16.bf16.f32 " \
        "{%0,%1,%2,%3}, {%4,%5,%6,%7}, {%8,%9}, {%0,%1,%2,%3};" \
        : "+f"((c)[0]), "+f"((c)[1]), "+f"((c)[2]), "+f"((c)[3]) \
        : "r"((a)[0]), "r"((a)[1]), "r"((a)[2]), "r"((a)[3]), "r"((b)[0]), "r"((b)[1]))

// ================= scratch =================
__device__ float g_q [PBP * PDM];
__device__ float g_kb[PBP * PDM];
__device__ float g_vb[PBP * PDM];
__device__ float g_qk[PBP * PH * PF];
__device__ float g_sb[PB * PH * PP * PP];
__device__ float g_at[PB * PH * PP * PP];
__device__ float g_ar[PBP * PH * PF];
__device__ __nv_bfloat16 g_pe_hi[PBP * PDM];
__device__ __nv_bfloat16 g_pe_lo[PBP * PDM];
__device__ __nv_bfloat16 g_cb_hi[PBP * PDM];
__device__ __nv_bfloat16 g_cb_lo[PBP * PDM];
__device__ __nv_bfloat16 g_wt_hi[4 * 512 * 512];  // transposed [n][k]: Wq,Wk0,Wv0,Wo
__device__ __nv_bfloat16 g_wt_lo[4 * 512 * 512];

__device__ __forceinline__ void bsplit(float x, __nv_bfloat16& h, __nv_bfloat16& l)
{
    h = __float2bfloat16_rn(x);
    l = __float2bfloat16_rn(x - __bfloat162float(h));
}

// ================= conversion kernels =================
__global__ void __launch_bounds__(256) conv_pe_kernel(const float* __restrict__ pe)
{
    int idx = blockIdx.x * 256 + threadIdx.x;  // x4 floats
    float4 v = *(const float4*)(pe + (size_t)idx * 4);
    __nv_bfloat16 h[4], l[4];
    bsplit(v.x, h[0], l[0]); bsplit(v.y, h[1], l[1]);
    bsplit(v.z, h[2], l[2]); bsplit(v.w, h[3], l[3]);
    *(uint2*)(g_pe_hi + (size_t)idx * 4) = *(uint2*)h;
    *(uint2*)(g_pe_lo + (size_t)idx * 4) = *(uint2*)l;
}

// transpose first 512 rows of W[:,512] -> Wt[n][k], bf16 hi/lo
__global__ void __launch_bounds__(256) conv_w_kernel(const float* __restrict__ Wq,
                                                     const float* __restrict__ Wk,
                                                     const float* __restrict__ Wv,
                                                     const float* __restrict__ Wo)
{
    const int z = blockIdx.z;
    const float* W = (z == 0) ? Wq : (z == 1) ? Wk : (z == 2) ? Wv : Wo;
    __shared__ float tile[32][33];
    const int n0 = blockIdx.x * 32, k0 = blockIdx.y * 32;
    const int tx = threadIdx.x & 31, ty = threadIdx.x >> 5;
#pragma unroll
    for (int j = 0; j < 4; j++)
        tile[ty + j * 8][tx] = W[(size_t)(k0 + ty + j * 8) * 512 + n0 + tx];
    __syncthreads();
#pragma unroll
    for (int j = 0; j < 4; j++) {
        float v = tile[tx][ty + j * 8];
        __nv_bfloat16 h, l; bsplit(v, h, l);
        size_t o = (size_t)z * 262144 + (size_t)(n0 + ty + j * 8) * 512 + k0 + tx;
        g_wt_hi[o] = h; g_wt_lo[o] = l;
    }
}

// ================= warp-MMA GEMM: C[m0:+64, n0:+64] = A @ B^T (bf16 hi/lo split) =================
// A: [.][512] bf16 row-major (hi/lo), B: [n][k] bf16 (hi/lo), C: [.][512] f32.
// Block = 128 threads (4 warps), warp tile 32x32, K-chunks of 64.
__device__ __forceinline__ void mma_gemm64(const __nv_bfloat16* __restrict__ Ahi,
                                           const __nv_bfloat16* __restrict__ Alo,
                                           const __nv_bfloat16* __restrict__ Bhi,
                                           const __nv_bfloat16* __restrict__ Blo,
                                           float* __restrict__ C, int m0, int n0)
{
    __shared__ __nv_bfloat16 sAh[4096], sAl[4096], sBh[4096], sBl[4096];  // 64 rows x 64 bf16, SW128
    const int tid = threadIdx.x, lane = tid & 31, wid = tid >> 5;
    const int wm = (wid & 1) * 32, wn = (wid >> 1) * 32;
    const int lr = tid >> 1, lh = tid & 1;  // gmem->smem: row, 32-bf16 half

    const uint32_t bAh = smem_to_u32(sAh), bAl = smem_to_u32(sAl);
    const uint32_t bBh = smem_to_u32(sBh), bBl = smem_to_u32(sBl);

    // per-lane ldmatrix coordinates
    const uint32_t rowA = wm + (lane & 15);
    const uint32_t kbA  = (lane >> 4) * 16;
    const uint32_t rowB = wn + (lane & 7) + ((lane >> 4) << 3);
    const uint32_t kbB  = ((lane >> 3) & 1) * 16;

    float c[2][4][4] = {};

    for (int ch = 0; ch < 8; ch++) {
        const int k0 = ch * 64;
        {
            const uint4* gah = (const uint4*)(Ahi + (size_t)(m0 + lr) * 512 + k0 + lh * 32);
            const uint4* gal = (const uint4*)(Alo + (size_t)(m0 + lr) * 512 + k0 + lh * 32);
            const uint4* gbh = (const uint4*)(Bhi + (size_t)(n0 + lr) * 512 + k0 + lh * 32);
            const uint4* gbl = (const uint4*)(Blo + (size_t)(n0 + lr) * 512 + k0 + lh * 32);
#pragma unroll
            for (int j = 0; j < 4; j++) {
                uint32_t o = SW128((uint32_t)(lr * 128 + lh * 64 + j * 16));
                *(uint4*)((char*)sAh + o) = gah[j];
                *(uint4*)((char*)sAl + o) = gal[j];
                *(uint4*)((char*)sBh + o) = gbh[j];
                *(uint4*)((char*)sBl + o) = gbl[j];
            }
        }
        __syncthreads();

#pragma unroll
        for (int ks = 0; ks < 4; ks++) {
            const uint32_t kA = ks * 32 + kbA;
            const uint32_t kB = ks * 32 + kbB;
            const uint32_t oA0 = SW128(rowA * 128 + kA);
            const uint32_t oA1 = SW128((rowA + 16) * 128 + kA);
            const uint32_t oB0 = SW128(rowB * 128 + kB);
            const uint32_t oB1 = SW128((rowB + 16) * 128 + kB);

            uint32_t ah0[4], ah1[4], al0[4], al1[4];
            LDMX4(ah0, bAh + oA0); LDMX4(ah1, bAh + oA1);
            LDMX4(al0, bAl + oA0); LDMX4(al1, bAl + oA1);
            uint32_t bh0[4], bh1[4], bl0[4], bl1[4];
            LDMX4(bh0, bBh + oB0); LDMX4(bh1, bBh + oB1);
            LDMX4(bl0, bBl + oB0); LDMX4(bl1, bBl + oB1);

            uint32_t* Ah[2] = { ah0, ah1 };
            uint32_t* Al[2] = { al0, al1 };
            uint32_t* Bh[4] = { bh0, bh0 + 2, bh1, bh1 + 2 };
            uint32_t* Bl[4] = { bl0, bl0 + 2, bl1, bl1 + 2 };
#pragma unroll
            for (int mt = 0; mt < 2; mt++) {
#pragma unroll
                for (int j = 0; j < 4; j++) {
                    MMA_BF16(c[mt][j], Ah[mt], Bh[j]);
                    MMA_BF16(c[mt][j], Ah[mt], Bl[j]);
                    MMA_BF16(c[mt][j], Al[mt], Bh[j]);
                }
            }
        }
        __syncthreads();
    }

    // epilogue: fragment (g = lane>>2, cc = (lane&3)*2)
    const int g = lane >> 2, cc = (lane & 3) * 2;
#pragma unroll
    for (int mt = 0; mt < 2; mt++)
#pragma unroll
        for (int j = 0; j < 4; j++) {
            int row = m0 + wm + mt * 16 + g;
            int col = n0 + wn + j * 8 + cc;
            *(float2*)(C + (size_t)row * 512 + col) = make_float2(c[mt][j][0], c[mt][j][1]);
            *(float2*)(C + (size_t)(row + 8) * 512 + col) = make_float2(c[mt][j][2], c[mt][j][3]);
        }
}

__global__ void __launch_bounds__(128) proj_mma_kernel()
{
    const int z = blockIdx.z;
    float* C = (z == 0) ? g_q : (z == 1) ? g_kb : g_vb;
    mma_gemm64(g_pe_hi, g_pe_lo, g_wt_hi + (size_t)z * 262144, g_wt_lo + (size_t)z * 262144,
               C, blockIdx.y * 64, blockIdx.x * 64);
}

__global__ void __launch_bounds__(128) final_mma_kernel(float* __restrict__ out)
{
    mma_gemm64(g_cb_hi, g_cb_lo, g_wt_hi + 3 * 262144, g_wt_lo + 3 * 262144,
               out, blockIdx.y * 64, blockIdx.x * 64);
}

// ================= K2: qk[m][h][f] = sum_d q[m][h*64+d] * Wk[512+f][h*64+d] =================
__global__ void __launch_bounds__(256) qk_kernel(const float* __restrict__ Wk)
{
    const int h = blockIdx.y;
    const int m0 = blockIdx.x * 64;
    __shared__ float Qt[64 * 68];
    __shared__ float Wt[64 * 68];
    const int tid = threadIdx.x, tx = tid & 15, ty = tid >> 4;
    const int lr = tid >> 4, lc4 = tid & 15;

#pragma unroll
    for (int i = 0; i < 4; i++) {
        int r = i * 16 + lr;
        float4 v = *(const float4*)(g_q + (size_t)(m0 + r) * 512 + h * 64 + lc4 * 4);
        Qt[(lc4 * 4 + 0) * 68 + r] = v.x; Qt[(lc4 * 4 + 1) * 68 + r] = v.y;
        Qt[(lc4 * 4 + 2) * 68 + r] = v.z; Qt[(lc4 * 4 + 3) * 68 + r] = v.w;
    }
    for (int fc = 0; fc < 2; fc++) {
        __syncthreads();
#pragma unroll
        for (int i = 0; i < 4; i++) {
            int f = i * 16 + lr;
            float4 v = *(const float4*)(Wk + (size_t)(512 + fc * 64 + f) * 512 + h * 64 + lc4 * 4);
            Wt[(lc4 * 4 + 0) * 68 + f] = v.x; Wt[(lc4 * 4 + 1) * 68 + f] = v.y;
            Wt[(lc4 * 4 + 2) * 68 + f] = v.z; Wt[(lc4 * 4 + 3) * 68 + f] = v.w;
        }
        __syncthreads();
        ulonglong2 acc[4];
#pragma unroll
        for (int i = 0; i < 4; i++) acc[i] = make_ulonglong2(0ull, 0ull);
#pragma unroll
        for (int d = 0; d < 64; d++) {
            float4 a4 = *(const float4*)&Qt[d * 68 + ty * 4];
            float4 b4 = *(const float4*)&Wt[d * 68 + tx * 4];
            u64 bp0 = *(u64*)&b4.x, bp1 = *(u64*)&b4.z;
            u64 a0 = pack_dup(a4.x), a1 = pack_dup(a4.y);
            u64 a2 = pack_dup(a4.z), a3 = pack_dup(a4.w);
            ffma2(acc[0].x, a0, bp0); ffma2(acc[0].y, a0, bp1);
            ffma2(acc[1].x, a1, bp0); ffma2(acc[1].y, a1, bp1);
            ffma2(acc[2].x, a2, bp0); ffma2(acc[2].y, a2, bp1);
            ffma2(acc[3].x, a3, bp0); ffma2(acc[3].y, a3, bp1);
        }
#pragma unroll
        for (int i = 0; i < 4; i++)
            *(float4*)(g_qk + (size_t)(m0 + ty * 4 + i) * (PH * PF) + h * PF + fc * 64 + tx * 4) =
                *(float4*)&acc[i];
    }
}

// ================= K3: scores_base =================
__global__ void __launch_bounds__(256) sbase_kernel()
{
    const int b = blockIdx.x, h = blockIdx.y;
    __shared__ float Qt[64 * 68];
    __shared__ float Kt[64 * 68];
    const int tid = threadIdx.x, tx = tid & 15, ty = tid >> 4;
    const int lr = tid >> 4, lc4 = tid & 15;

#pragma unroll
    for (int i = 0; i < 4; i++) {
        int r = i * 16 + lr;
        float4 vq = *(const float4*)(g_q  + (size_t)(b * 64 + r) * 512 + h * 64 + lc4 * 4);
        float4 vk = *(const float4*)(g_kb + (size_t)(b * 64 + r) * 512 + h * 64 + lc4 * 4);
        Qt[(lc4 * 4 + 0) * 68 + r] = vq.x; Qt[(lc4 * 4 + 1) * 68 + r] = vq.y;
        Qt[(lc4 * 4 + 2) * 68 + r] = vq.z; Qt[(lc4 * 4 + 3) * 68 + r] = vq.w;
        Kt[(lc4 * 4 + 0) * 68 + r] = vk.x; Kt[(lc4 * 4 + 1) * 68 + r] = vk.y;
        Kt[(lc4 * 4 + 2) * 68 + r] = vk.z; Kt[(lc4 * 4 + 3) * 68 + r] = vk.w;
    }
    __syncthreads();

    ulonglong2 acc[4];
#pragma unroll
    for (int i = 0; i < 4; i++) acc[i] = make_ulonglong2(0ull, 0ull);
#pragma unroll
    for (int d = 0; d < 64; d++) {
        float4 a4 = *(const float4*)&Qt[d * 68 + ty * 4];
        float4 b4 = *(const float4*)&Kt[d * 68 + tx * 4];
        u64 bp0 = *(u64*)&b4.x, bp1 = *(u64*)&b4.z;
        u64 a0 = pack_dup(a4.x), a1 = pack_dup(a4.y);
        u64 a2 = pack_dup(a4.z), a3 = pack_dup(a4.w);
        ffma2(acc[0].x, a0, bp0); ffma2(acc[0].y, a0, bp1);
        ffma2(acc[1].x, a1, bp0); ffma2(acc[1].y, a1, bp1);
        ffma2(acc[2].x, a2, bp0); ffma2(acc[2].y, a2, bp1);
        ffma2(acc[3].x, a3, bp0); ffma2(acc[3].y, a3, bp1);
    }
    float* out = g_sb + (size_t)((b * 8 + h) * 64) * 64;
#pragma unroll
    for (int i = 0; i < 4; i++)
        *(float4*)(out + (ty * 4 + i) * 64 + tx * 4) = *(float4*)&acc[i];
}

// ================= K4: fused attn (scores_rel + softmax + ar) =================
__global__ void __launch_bounds__(256, 3) attn_kernel(const float* __restrict__ rf)
{
    const int bq = blockIdx.x;
    const int b = bq >> 6, q = bq & 63;
    __shared__ float rf_s[64 * 132];
    __shared__ float qk_s[8 * 132];
    __shared__ float s_s [8 * 64];
    __shared__ float at_s[8 * 68];
    const int tid = threadIdx.x;

    const float4* rfg = (const float4*)(rf + (size_t)bq * 8192);
    float4* rf4 = (float4*)rf_s;
#pragma unroll
    for (int i = 0; i < 8; i++) {
        int idx = i * 256 + tid;
        rf4[(idx >> 5) * 33 + (idx & 31)] = rfg[idx];
    }
    ((float4*)qk_s)[(tid >> 5) * 33 + (tid & 31)] =
        ((const float4*)(g_qk + (size_t)bq * (PH * PF)))[tid];
    __syncthreads();

    // scores: warp covers 8 h x 4 p -> rf reads become 4-address + broadcast
#pragma unroll
    for (int rep = 0; rep < 2; rep++) {
        int o = rep * 256 + tid;
        int h = o & 7, p = o >> 3;
        const float4* qr = (const float4*)qk_s + h * 33;
        const float4* rr = rf4 + p * 33;
        u64 acc2 = 0ull;
#pragma unroll 8
        for (int f4 = 0; f4 < 32; f4++) {
            float4 a = qr[f4], r = rr[f4];
            ffma2(acc2, *(u64*)&a.x, *(u64*)&r.x);
            ffma2(acc2, *(u64*)&a.z, *(u64*)&r.z);
        }
        float lo, hi; unpack2(lo, hi, acc2);
        float sbv = g_sb[(size_t)((b * 8 + h) * 64 + q) * 64 + p];
        s_s[h * 64 + p] = 0.125f * (lo + hi + sbv);
    }
    __syncthreads();

    {
        int w = tid >> 5, l = tid & 31;
        float v0 = s_s[w * 64 + l], v1 = s_s[w * 64 + 32 + l];
        float m = fmaxf(v0, v1);
#pragma unroll
        for (int off = 16; off; off >>= 1) m = fmaxf(m, __shfl_xor_sync(0xffffffffu, m, off));
        float e0 = __expf(v0 - m), e1 = __expf(v1 - m);
        float s = e0 + e1;
#pragma unroll
        for (int off = 16; off; off >>= 1) s += __shfl_xor_sync(0xffffffffu, s, off);
        float inv = 1.f / s;
        float a0 = e0 * inv, a1 = e1 * inv;
        at_s[w * 68 + l] = a0; at_s[w * 68 + 32 + l] = a1;
        float* ag = g_at + (size_t)((b * 8 + w) * 64 + q) * 64;
        ag[l] = a0; ag[32 + l] = a1;
    }
    __syncthreads();

    {
        int h = tid >> 5, f4 = tid & 31;
        const float* ah = at_s + h * 68;
        ulonglong2 acc = make_ulonglong2(0ull, 0ull);
#pragma unroll 8
        for (int p = 0; p < 64; p++) {
            u64 ad = pack_dup(ah[p]);
            float4 r = rf4[p * 33 + f4];
            ffma2(acc.x, ad, *(u64*)&r.x);
            ffma2(acc.y, ad, *(u64*)&r.z);
        }
        ((float4*)(g_ar + (size_t)bq * (PH * PF)))[tid] = *(float4*)&acc;
    }
}

// ================= K5+K6 merged: cb = attn@v_base + ar@Wv_f -> bf16 hi/lo =================
__global__ void __launch_bounds__(256) outmerge_kernel(const float* __restrict__ Wv)
{
    const int b = blockIdx.x, h = blockIdx.y;
    __shared__ float S1[64 * 68];
    __shared__ float S2[64 * 68];
    const int tid = threadIdx.x, tx = tid & 15, ty = tid >> 4;
    const int lr = tid >> 4, lc4 = tid & 15;

    ulonglong2 acc[4];
#pragma unroll
    for (int i = 0; i < 4; i++) acc[i] = make_ulonglong2(0ull, 0ull);

    // phase A: outbase — S1 = attn^T [p][q], S2 = v_base [p][d]
#pragma unroll
    for (int i = 0; i < 4; i++) {
        int r = i * 16 + lr;
        float4 va = *(const float4*)(g_at + (size_t)((b * 8 + h) * 64 + r) * 64 + lc4 * 4);
        S1[(lc4 * 4 + 0) * 68 + r] = va.x; S1[(lc4 * 4 + 1) * 68 + r] = va.y;
        S1[(lc4 * 4 + 2) * 68 + r] = va.z; S1[(lc4 * 4 + 3) * 68 + r] = va.w;
        *(float4*)&S2[r * 68 + lc4 * 4] =
            *(const float4*)(g_vb + (size_t)(b * 64 + r) * 512 + h * 64 + lc4 * 4);
    }
    __syncthreads();
#pragma unroll
    for (int p = 0; p < 64; p++) {
        float4 a4 = *(const float4*)&S1[p * 68 + ty * 4];
        float4 b4 = *(const float4*)&S2[p * 68 + tx * 4];
        u64 bp0 = *(u64*)&b4.x, bp1 = *(u64*)&b4.z;
        u64 a0 = pack_dup(a4.x), a1 = pack_dup(a4.y);
        u64 a2 = pack_dup(a4.z), a3 = pack_dup(a4.w);
        ffma2(acc[0].x, a0, bp0); ffma2(acc[0].y, a0, bp1);
        ffma2(acc[1].x, a1, bp0); ffma2(acc[1].y, a1, bp1);
        ffma2(acc[2].x, a2, bp0); ffma2(acc[2].y, a2, bp1);
        ffma2(acc[3].x, a3, bp0); ffma2(acc[3].y, a3, bp1);
    }

    // phase B: outrel — S1 = ar^T [f][m], S2 = Wv_f [f][d]
    const int m0 = b * 64;
    for (int fc = 0; fc < 2; fc++) {
        __syncthreads();
#pragma unroll
        for (int i = 0; i < 4; i++) {
            int r = i * 16 + lr;
            float4 va = *(const float4*)(g_ar + (size_t)(m0 + r) * (PH * PF) + h * PF + fc * 64 + lc4 * 4);
            S1[(lc4 * 4 + 0) * 68 + r] = va.x; S1[(lc4 * 4 + 1) * 68 + r] = va.y;
            S1[(lc4 * 4 + 2) * 68 + r] = va.z; S1[(lc4 * 4 + 3) * 68 + r] = va.w;
            *(float4*)&S2[r * 68 + lc4 * 4] =
                *(const float4*)(Wv + (size_t)(512 + fc * 64 + r) * 512 + h * 64 + lc4 * 4);
        }
        __syncthreads();
#pragma unroll
        for (int f = 0; f < 64; f++) {
            float4 a4 = *(const float4*)&S1[f * 68 + ty * 4];
            float4 b4 = *(const float4*)&S2[f * 68 + tx * 4];
            u64 bp0 = *(u64*)&b4.x, bp1 = *(u64*)&b4.z;
            u64 a0 = pack_dup(a4.x), a1 = pack_dup(a4.y);
            u64 a2 = pack_dup(a4.z), a3 = pack_dup(a4.w);
            ffma2(acc[0].x, a0, bp0); ffma2(acc[0].y, a0, bp1);
            ffma2(acc[1].x, a1, bp0); ffma2(acc[1].y, a1, bp1);
            ffma2(acc[2].x, a2, bp0); ffma2(acc[2].y, a2, bp1);
            ffma2(acc[3].x, a3, bp0); ffma2(acc[3].y, a3, bp1);
        }
    }

    // epilogue: bf16 split -> g_cb_hi / g_cb_lo
#pragma unroll
    for (int i = 0; i < 4; i++) {
        float4 v = *(float4*)&acc[i];
        __nv_bfloat16 hb[4], lb[4];
        bsplit(v.x, hb[0], lb[0]); bsplit(v.y, hb[1], lb[1]);
        bsplit(v.z, hb[2], lb[2]); bsplit(v.w, hb[3], lb[3]);
        size_t o = (size_t)(b * 64 + ty * 4 + i) * 512 + h * 64 + tx * 4;
        *(uint2*)(g_cb_hi + o) = *(uint2*)hb;
        *(uint2*)(g_cb_lo + o) = *(uint2*)lb;
    }
}

// ================= launch =================
extern "C" void kernel_launch(void* const* d_in, const int* in_sizes, int n_in,
                              void* d_out, int out_size)
{
    (void)in_sizes; (void)n_in; (void)out_size;
    const float* pe = (const float*)d_in[0];
    const float* rf = (const float*)d_in[1];
    const float* Wq = (const float*)d_in[3];
    const float* Wk = (const float*)d_in[4];
    const float* Wv = (const float*)d_in[5];
    const float* Wo = (const float*)d_in[6];
    float* out = (float*)d_out;

    conv_pe_kernel  <<<512, 256>>>(pe);
    conv_w_kernel   <<<dim3(16, 16, 4), 256>>>(Wq, Wk, Wv, Wo);
    proj_mma_kernel <<<dim3(8, 16, 3), 128>>>();
    qk_kernel       <<<dim3(16, 8), 256>>>(Wk);
    sbase_kernel    <<<dim3(16, 8), 256>>>();
    attn_kernel     <<<dim3(1024), 256>>>(rf);
    outmerge_kernel <<<dim3(16, 8), 256>>>(Wv);
    final_mma_kernel<<<dim3(8, 16), 128>>>(out);
}